// round 4
// baseline (speedup 1.0000x reference)
#include <cuda_runtime.h>
#include <math_constants.h>

// Problem constants (fixed shapes for this problem instance)
#define PB 8192      // batch rows
#define PK 8192      // codebook size
#define PD 512       // embedding dim per codebook
#define LDZ 1024     // z_e_x row stride (2*PD)
#define LDS_SCORES 16384  // scores row stride (2*PK)

// GEMM tiling
#define BM 128
#define BN 128
#define BK 16
#define NTHREADS 256

// ---------------------------------------------------------------------------
// Kernel 1: scores[b, g*8192 + k] = dot(z_e_x[b, g*512 : g*512+512], W_g[k, :])
// blockIdx.z = g (0: W_a, 1: W_v). Classic double-buffered SGEMM, 8x8 regs/thread.
// ---------------------------------------------------------------------------
__global__ __launch_bounds__(NTHREADS, 2)
void vq_gemm_kernel(const float* __restrict__ Z,
                    const float* __restrict__ Wa,
                    const float* __restrict__ Wv,
                    float* __restrict__ scores)
{
    const int g = blockIdx.z;
    const float* __restrict__ W = g ? Wv : Wa;
    const float* __restrict__ A = Z + g * PD;   // row stride LDZ

    const int bm = blockIdx.y * BM;
    const int bn = blockIdx.x * BN;

    __shared__ float As[2][BK][BM];
    __shared__ float Bs[2][BK][BN];

    const int tid = threadIdx.x;
    const int ty  = tid >> 4;   // 0..15
    const int tx  = tid & 15;   // 0..15

    // loader mapping: thread covers rows (lrow, lrow+64), 4 consecutive k at lk
    const int lrow = tid >> 2;        // 0..63
    const int lk   = (tid & 3) * 4;   // 0,4,8,12

    const float* Ag = A + (size_t)(bm + lrow) * LDZ + lk;
    const float* Wg = W + (size_t)(bn + lrow) * PD  + lk;

    float acc[8][8];
#pragma unroll
    for (int i = 0; i < 8; i++)
#pragma unroll
        for (int j = 0; j < 8; j++) acc[i][j] = 0.f;

    float4 pa0, pa1, pb0, pb1;

    // prefetch k-tile 0
    pa0 = *(const float4*)(Ag);
    pa1 = *(const float4*)(Ag + (size_t)64 * LDZ);
    pb0 = *(const float4*)(Wg);
    pb1 = *(const float4*)(Wg + (size_t)64 * PD);

#define STS_TILE(st)                                                                   \
    As[st][lk+0][lrow]    = pa0.x; As[st][lk+1][lrow]    = pa0.y;                      \
    As[st][lk+2][lrow]    = pa0.z; As[st][lk+3][lrow]    = pa0.w;                      \
    As[st][lk+0][lrow+64] = pa1.x; As[st][lk+1][lrow+64] = pa1.y;                      \
    As[st][lk+2][lrow+64] = pa1.z; As[st][lk+3][lrow+64] = pa1.w;                      \
    Bs[st][lk+0][lrow]    = pb0.x; Bs[st][lk+1][lrow]    = pb0.y;                      \
    Bs[st][lk+2][lrow]    = pb0.z; Bs[st][lk+3][lrow]    = pb0.w;                      \
    Bs[st][lk+0][lrow+64] = pb1.x; Bs[st][lk+1][lrow+64] = pb1.y;                      \
    Bs[st][lk+2][lrow+64] = pb1.z; Bs[st][lk+3][lrow+64] = pb1.w;

    STS_TILE(0);
    __syncthreads();

    const int NK = PD / BK;  // 32
    int s = 0;
    for (int kt = 0; kt < NK; kt++) {
        // prefetch next k-tile from global while computing current
        if (kt + 1 < NK) {
            const float* Ag2 = Ag + (kt + 1) * BK;
            const float* Wg2 = Wg + (kt + 1) * BK;
            pa0 = *(const float4*)(Ag2);
            pa1 = *(const float4*)(Ag2 + (size_t)64 * LDZ);
            pb0 = *(const float4*)(Wg2);
            pb1 = *(const float4*)(Wg2 + (size_t)64 * PD);
        }

#pragma unroll
        for (int kk = 0; kk < BK; kk++) {
            float4 a0 = *(const float4*)&As[s][kk][ty * 8];
            float4 a1 = *(const float4*)&As[s][kk][ty * 8 + 4];
            float4 b0 = *(const float4*)&Bs[s][kk][tx * 8];
            float4 b1 = *(const float4*)&Bs[s][kk][tx * 8 + 4];
            float a[8] = {a0.x, a0.y, a0.z, a0.w, a1.x, a1.y, a1.z, a1.w};
            float b[8] = {b0.x, b0.y, b0.z, b0.w, b1.x, b1.y, b1.z, b1.w};
#pragma unroll
            for (int i = 0; i < 8; i++)
#pragma unroll
                for (int j = 0; j < 8; j++)
                    acc[i][j] = fmaf(a[i], b[j], acc[i][j]);
        }

        if (kt + 1 < NK) {
            const int ns = s ^ 1;
            STS_TILE(ns);
        }
        __syncthreads();
        s ^= 1;
    }
#undef STS_TILE

    // epilogue: write scores tile (row stride 2K, column offset g*K)
    float* crow = scores + (size_t)(bm + ty * 8) * LDS_SCORES + (size_t)g * PK + bn + tx * 8;
#pragma unroll
    for (int i = 0; i < 8; i++) {
        float4 v0 = make_float4(acc[i][0], acc[i][1], acc[i][2], acc[i][3]);
        float4 v1 = make_float4(acc[i][4], acc[i][5], acc[i][6], acc[i][7]);
        *(float4*)(crow + (size_t)i * LDS_SCORES)     = v0;
        *(float4*)(crow + (size_t)i * LDS_SCORES + 4) = v1;
    }
}

// ---------------------------------------------------------------------------
// Kernel 2: per (row, codebook): argmax over 8192 scores (first-index tie-break,
// matching jnp.argmax), then gather W[idx] into z_q_st and z_q output slots.
// ---------------------------------------------------------------------------
__global__ __launch_bounds__(256)
void vq_argmax_gather_kernel(const float* __restrict__ scores,
                             const float* __restrict__ Wa,
                             const float* __restrict__ Wv,
                             float* __restrict__ out_st,
                             float* __restrict__ out_q)
{
    const int r = blockIdx.x;   // 0..8191
    const int g = blockIdx.y;   // 0..1
    const int tid = threadIdx.x;

    const float* __restrict__ srow = scores + (size_t)r * LDS_SCORES + (size_t)g * PK;

    float best = -CUDART_INF_F;
    int   bidx = 0;
    // ascending k per thread -> per-thread first-max semantics preserved
    for (int k = tid; k < PK; k += 256) {
        float v = srow[k];
        if (v > best) { best = v; bidx = k; }
    }

    __shared__ float sv[256];
    __shared__ int   si[256];
    sv[tid] = best;
    si[tid] = bidx;
    __syncthreads();

#pragma unroll
    for (int stride = 128; stride > 0; stride >>= 1) {
        if (tid < stride) {
            float v2 = sv[tid + stride];
            int   i2 = si[tid + stride];
            if (v2 > sv[tid] || (v2 == sv[tid] && i2 < si[tid])) {
                sv[tid] = v2;
                si[tid] = i2;
            }
        }
        __syncthreads();
    }
    const int idx = si[0];

    const float* __restrict__ Wrow = (g ? Wv : Wa) + (size_t)idx * PD;
    float* st = out_st + (size_t)r * LDZ + (size_t)g * PD;
    float* q  = out_q  + (size_t)r * LDZ + (size_t)g * PD;

    // 512 floats = 128 float4; 256 threads -> guard
    if (tid < 128) {
        float4 w = *(const float4*)(Wrow + tid * 4);
        *(float4*)(st + tid * 4) = w;
        *(float4*)(q  + tid * 4) = w;
    }
}

// ---------------------------------------------------------------------------
// Harness entry
// ---------------------------------------------------------------------------
extern "C" void kernel_launch(void* const* d_in, const int* in_sizes, int n_in,
                              void* d_out, int out_size)
{
    const float* Z  = (const float*)d_in[0];  // [8192, 1024]
    const float* Wa = (const float*)d_in[1];  // [8192, 512]
    const float* Wv = (const float*)d_in[2];  // [8192, 512]

    float* out    = (float*)d_out;
    float* out_st = out;                                   // [B, 2D]
    float* out_q  = out + (size_t)PB * LDZ;                // [B, 2D]
    float* scores = out + (size_t)2 * PB * LDZ;            // [B, 2K]

    dim3 ggrid(PK / BN, PB / BM, 2);   // (64, 64, 2)
    vq_gemm_kernel<<<ggrid, NTHREADS>>>(Z, Wa, Wv, scores);

    dim3 agrid(PB, 2);
    vq_argmax_gather_kernel<<<agrid, 256>>>(scores, Wa, Wv, out_st, out_q);
}

// round 6
// speedup vs baseline: 1.3012x; 1.3012x over previous
#include <cuda_runtime.h>
#include <math_constants.h>
#include <cstdint>

// ---------------- problem constants ----------------
#define PB 8192      // batch rows
#define PK 8192      // codebook size
#define PD 512       // dim per codebook
#define LDZ 1024     // z_e_x row stride (2*PD)
#define LDSC 16384   // scores row stride (2*PK)

// ---------------- GEMM tiling ----------------
#define BM 128
#define BN 128
#define BK 16
#define NK (PD / BK)        // 32 k-iterations
#define PADROW 136          // floats per smem row (128 + 8 pad: conflict-free frags)
#define STAGE_F (2 * BK * PADROW)   // A tile + B tile per stage, in floats

// ---------------- helpers ----------------
static __device__ __forceinline__ float tf32_round(float x) {
    uint32_t r;
    asm("cvt.rna.tf32.f32 %0, %1;" : "=r"(r) : "f"(x));
    return __uint_as_float(r);
}

// D += A(tf32) * B(tf32), m16n8k8
static __device__ __forceinline__ void mma1688(float* c, const uint32_t* a, const uint32_t* b) {
    asm volatile(
        "mma.sync.aligned.m16n8k8.row.col.f32.tf32.tf32.f32 "
        "{%0,%1,%2,%3}, {%4,%5,%6,%7}, {%8,%9}, {%0,%1,%2,%3};"
        : "+f"(c[0]), "+f"(c[1]), "+f"(c[2]), "+f"(c[3])
        : "r"(a[0]), "r"(a[1]), "r"(a[2]), "r"(a[3]), "r"(b[0]), "r"(b[1]));
}

// ---------------------------------------------------------------------------
// Kernel 1: 3xTF32 mma.sync dual-GEMM.
// scores[b, g*PK + n] = dot(Z[b, g*PD:(g+1)*PD], W_g[n, :]) at ~fp32 precision.
// ---------------------------------------------------------------------------
__global__ __launch_bounds__(256, 1)
void vq_gemm_mma(const float* __restrict__ Z,
                 const float* __restrict__ Wa,
                 const float* __restrict__ Wv,
                 float* __restrict__ scores)
{
    __shared__ float sm[2][STAGE_F];   // [stage][ A:16x136 | B:16x136 ]
    float* const sA0 = &sm[0][0];
    float* const sB0 = &sm[0][BK * PADROW];

    const int tid  = threadIdx.x;
    const int lane = tid & 31;
    const int w    = tid >> 5;
    const int wm   = w >> 2;   // 0..1 -> 64-row slab
    const int wn   = w & 3;    // 0..3 -> 32-col slab
    const int g    = blockIdx.z;
    const int bm   = blockIdx.y * BM;
    const int bn   = blockIdx.x * BN;

    const float* __restrict__ W = g ? Wv : Wa;
    const float* __restrict__ A = Z + g * PD;

    // loader mapping: thread covers row tid>>1, 8 k-floats starting (tid&1)*8
    const int lr = tid >> 1;
    const int kq = (tid & 1) * 8;
    const float* Ag = A + (size_t)(bm + lr) * LDZ + kq;
    const float* Wg = W + (size_t)(bn + lr) * PD  + kq;

    float acc[4][4][4];
#pragma unroll
    for (int i = 0; i < 4; i++)
#pragma unroll
        for (int j = 0; j < 4; j++)
#pragma unroll
            for (int q = 0; q < 4; q++) acc[i][j][q] = 0.f;

    // prefetch k-tile 0
    float4 va0 = *(const float4*)(Ag);
    float4 va1 = *(const float4*)(Ag + 4);
    float4 vb0 = *(const float4*)(Wg);
    float4 vb1 = *(const float4*)(Wg + 4);

    for (int kt = 0; kt < NK; kt++) {
        const int s = kt & 1;
        float* sA = sA0 + s * STAGE_F;
        float* sB = sB0 + s * STAGE_F;

        // ---- store current tile (transposed [k][row]) ----
        {
            const float* f;
            f = (const float*)&va0;
#pragma unroll
            for (int c = 0; c < 4; c++) sA[(kq + c) * PADROW + lr] = f[c];
            f = (const float*)&va1;
#pragma unroll
            for (int c = 0; c < 4; c++) sA[(kq + 4 + c) * PADROW + lr] = f[c];
            f = (const float*)&vb0;
#pragma unroll
            for (int c = 0; c < 4; c++) sB[(kq + c) * PADROW + lr] = f[c];
            f = (const float*)&vb1;
#pragma unroll
            for (int c = 0; c < 4; c++) sB[(kq + 4 + c) * PADROW + lr] = f[c];
        }
        __syncthreads();

        // ---- prefetch next tile ----
        if (kt + 1 < NK) {
            const float* ag = Ag + (kt + 1) * BK;
            const float* wg = Wg + (kt + 1) * BK;
            va0 = *(const float4*)(ag);
            va1 = *(const float4*)(ag + 4);
            vb0 = *(const float4*)(wg);
            vb1 = *(const float4*)(wg + 4);
        }

        // ---- compute: 2 k-slabs of 8 ----
#pragma unroll
        for (int kb = 0; kb < BK; kb += 8) {
            const int kr = kb + (lane & 3);
            // A fragments: hi/lo split in registers
            uint32_t ah[4][4], al[4][4];
#pragma unroll
            for (int mt = 0; mt < 4; mt++) {
                const int m_ = wm * 64 + mt * 16 + (lane >> 2);
                float x0 = sA[kr * PADROW + m_];
                float x1 = sA[kr * PADROW + m_ + 8];
                float x2 = sA[(kr + 4) * PADROW + m_];
                float x3 = sA[(kr + 4) * PADROW + m_ + 8];
                float h0 = tf32_round(x0), h1 = tf32_round(x1);
                float h2 = tf32_round(x2), h3 = tf32_round(x3);
                ah[mt][0] = __float_as_uint(h0); al[mt][0] = __float_as_uint(x0 - h0);
                ah[mt][1] = __float_as_uint(h1); al[mt][1] = __float_as_uint(x1 - h1);
                ah[mt][2] = __float_as_uint(h2); al[mt][2] = __float_as_uint(x2 - h2);
                ah[mt][3] = __float_as_uint(h3); al[mt][3] = __float_as_uint(x3 - h3);
            }
#pragma unroll
            for (int nt = 0; nt < 4; nt++) {
                const int n_ = wn * 32 + nt * 8 + (lane >> 2);
                float y0 = sB[kr * PADROW + n_];
                float y1 = sB[(kr + 4) * PADROW + n_];
                float g0 = tf32_round(y0), g1 = tf32_round(y1);
                uint32_t bh[2] = { __float_as_uint(g0), __float_as_uint(g1) };
                uint32_t bl[2] = { __float_as_uint(y0 - g0), __float_as_uint(y1 - g1) };
#pragma unroll
                for (int mt = 0; mt < 4; mt++) {
                    mma1688(acc[mt][nt], ah[mt], bh);   // hi*hi
                    mma1688(acc[mt][nt], al[mt], bh);   // lo*hi
                    mma1688(acc[mt][nt], ah[mt], bl);   // hi*lo
                }
            }
        }
        __syncthreads();
    }

    // ---- epilogue: c0,c1 at (r, col), c2,c3 at (r+8, col) ----
    const size_t gcol = (size_t)g * PK + bn;
#pragma unroll
    for (int mt = 0; mt < 4; mt++) {
        const int r0 = bm + wm * 64 + mt * 16 + (lane >> 2);
#pragma unroll
        for (int nt = 0; nt < 4; nt++) {
            const int c0 = wn * 32 + nt * 8 + (lane & 3) * 2;
            float2 lo = make_float2(acc[mt][nt][0], acc[mt][nt][1]);
            float2 hi = make_float2(acc[mt][nt][2], acc[mt][nt][3]);
            *(float2*)(scores + (size_t)r0 * LDSC + gcol + c0)       = lo;
            *(float2*)(scores + (size_t)(r0 + 8) * LDSC + gcol + c0) = hi;
        }
    }
}

// ---------------------------------------------------------------------------
// Kernel 2: per (row, codebook): argmax over 8192 scores (first-index tie-break)
// then gather W[idx] into z_q_st and z_q. (82.6% DRAM — near roofline.)
// ---------------------------------------------------------------------------
__global__ __launch_bounds__(256)
void vq_argmax_gather_kernel(const float* __restrict__ scores,
                             const float* __restrict__ Wa,
                             const float* __restrict__ Wv,
                             float* __restrict__ out_st,
                             float* __restrict__ out_q)
{
    const int r = blockIdx.x;
    const int g = blockIdx.y;
    const int tid = threadIdx.x;

    const float* __restrict__ srow = scores + (size_t)r * LDSC + (size_t)g * PK;

    float best = -CUDART_INF_F;
    int   bidx = 0;
    for (int k = tid; k < PK; k += 256) {
        float v = srow[k];
        if (v > best) { best = v; bidx = k; }
    }

    __shared__ float sv[256];
    __shared__ int   si[256];
    sv[tid] = best;
    si[tid] = bidx;
    __syncthreads();

#pragma unroll
    for (int stride = 128; stride > 0; stride >>= 1) {
        if (tid < stride) {
            float v2 = sv[tid + stride];
            int   i2 = si[tid + stride];
            if (v2 > sv[tid] || (v2 == sv[tid] && i2 < si[tid])) {
                sv[tid] = v2;
                si[tid] = i2;
            }
        }
        __syncthreads();
    }
    const int idx = si[0];

    const float* __restrict__ Wrow = (g ? Wv : Wa) + (size_t)idx * PD;
    float* st = out_st + (size_t)r * LDZ + (size_t)g * PD;
    float* q  = out_q  + (size_t)r * LDZ + (size_t)g * PD;

    if (tid < 128) {
        float4 wv = *(const float4*)(Wrow + tid * 4);
        *(float4*)(st + tid * 4) = wv;
        *(float4*)(q  + tid * 4) = wv;
    }
}

// ---------------------------------------------------------------------------
// Harness entry
// ---------------------------------------------------------------------------
extern "C" void kernel_launch(void* const* d_in, const int* in_sizes, int n_in,
                              void* d_out, int out_size)
{
    const float* Z  = (const float*)d_in[0];  // [8192, 1024]
    const float* Wa = (const float*)d_in[1];  // [8192, 512]
    const float* Wv = (const float*)d_in[2];  // [8192, 512]

    float* out    = (float*)d_out;
    float* out_st = out;                         // [B, 2D]
    float* out_q  = out + (size_t)PB * LDZ;      // [B, 2D]
    float* scores = out + (size_t)2 * PB * LDZ;  // [B, 2K]

    dim3 ggrid(PK / BN, PB / BM, 2);   // (64, 64, 2)
    vq_gemm_mma<<<ggrid, 256>>>(Z, Wa, Wv, scores);

    dim3 agrid(PB, 2);
    vq_argmax_gather_kernel<<<agrid, 256>>>(scores, Wa, Wv, out_st, out_q);
}

// round 7
// speedup vs baseline: 1.5436x; 1.1863x over previous
#include <cuda_runtime.h>
#include <math_constants.h>
#include <cstdint>

// ---------------- problem constants ----------------
#define PB 8192      // batch rows
#define PK 8192      // codebook size
#define PD 512       // dim per codebook
#define LDZ 1024     // z_e_x row stride (2*PD)
#define LDSC 16384   // scores row stride (2*PK)

// ---------------- GEMM tiling ----------------
#define BM 128
#define BN 128
#define BK 16
#define NK (PD / BK)     // 32 k-iterations

// smem: bf16 tiles [row][k], 16 bf16 of payload padded to 24 (48B rows)
#define ROWB 48                         // bytes per smem row
#define T_BYTES (128 * ROWB)            // 6144 per tile buffer
#define STG_BYTES (4 * T_BYTES)         // Ah, Al, Bh, Bl = 24576
// offsets within a stage
#define OFF_AH 0
#define OFF_AL (T_BYTES)
#define OFF_BH (2 * T_BYTES)
#define OFF_BL (3 * T_BYTES)

// ---------------- helpers ----------------
// pack two f32 -> bf16x2 (k-even in low half)
static __device__ __forceinline__ uint32_t pack_bf16(float lo, float hi) {
    uint32_t r;
    asm("cvt.rn.bf16x2.f32 %0, %1, %2;" : "=r"(r) : "f"(hi), "f"(lo));
    return r;
}

// D += A(bf16) * B(bf16), m16n8k16
static __device__ __forceinline__ void mma16816(float* c, const uint32_t* a, const uint32_t* b) {
    asm volatile(
        "mma.sync.aligned.m16n8k16.row.col.f32.bf16.bf16.f32 "
        "{%0,%1,%2,%3}, {%4,%5,%6,%7}, {%8,%9}, {%0,%1,%2,%3};"
        : "+f"(c[0]), "+f"(c[1]), "+f"(c[2]), "+f"(c[3])
        : "r"(a[0]), "r"(a[1]), "r"(a[2]), "r"(a[3]), "r"(b[0]), "r"(b[1]));
}

// split 8 consecutive f32 (two float4) into packed bf16x2 hi[4] / lo[4]
static __device__ __forceinline__ void split8(const float4 v0, const float4 v1,
                                              uint32_t* h, uint32_t* l) {
    h[0] = pack_bf16(v0.x, v0.y);
    h[1] = pack_bf16(v0.z, v0.w);
    h[2] = pack_bf16(v1.x, v1.y);
    h[3] = pack_bf16(v1.z, v1.w);
    float r0 = v0.x - __uint_as_float(h[0] << 16);
    float r1 = v0.y - __uint_as_float(h[0] & 0xFFFF0000u);
    float r2 = v0.z - __uint_as_float(h[1] << 16);
    float r3 = v0.w - __uint_as_float(h[1] & 0xFFFF0000u);
    float r4 = v1.x - __uint_as_float(h[2] << 16);
    float r5 = v1.y - __uint_as_float(h[2] & 0xFFFF0000u);
    float r6 = v1.z - __uint_as_float(h[3] << 16);
    float r7 = v1.w - __uint_as_float(h[3] & 0xFFFF0000u);
    l[0] = pack_bf16(r0, r1);
    l[1] = pack_bf16(r2, r3);
    l[2] = pack_bf16(r4, r5);
    l[3] = pack_bf16(r6, r7);
}

// ---------------------------------------------------------------------------
// Kernel 1: split-bf16 (3-term) mma.sync dual-GEMM.
// scores[b, g*PK + n] = dot(Z[b, g*PD:(g+1)*PD], W_g[n, :]) at ~2^-17 precision.
// CTA: 128x128 tile, 8 warps (warp tile 64x32), double-buffered bf16 smem.
// ---------------------------------------------------------------------------
__global__ __launch_bounds__(256, 1)
void vq_gemm_bf16x2(const float* __restrict__ Z,
                    const float* __restrict__ Wa,
                    const float* __restrict__ Wv,
                    float* __restrict__ scores)
{
    __shared__ __align__(16) char sm[2 * STG_BYTES];   // 49152 B

    const int tid  = threadIdx.x;
    const int lane = tid & 31;
    const int w    = tid >> 5;
    const int wm   = w >> 2;   // 0..1 -> 64-row slab
    const int wn   = w & 3;    // 0..3 -> 32-col slab
    const int g    = blockIdx.z;
    const int bm   = blockIdx.y * BM;
    const int bn   = blockIdx.x * BN;

    const float* __restrict__ W = g ? Wv : Wa;
    const float* __restrict__ A = Z + g * PD;

    // loader mapping: thread covers row tid>>1, 8 k-floats starting (tid&1)*8
    const int lr  = tid >> 1;
    const int kh  = (tid & 1);            // which 8-k half
    const float* Ag = A + (size_t)(bm + lr) * LDZ + kh * 8;
    const float* Wg = W + (size_t)(bn + lr) * PD  + kh * 8;
    const int st_off = lr * ROWB + kh * 16;   // byte offset of this thread's 16B slot

    const int qr = lane >> 2;        // 0..7
    const int qc = (lane & 3) * 4;   // word byte-offset 0..12

    float acc[4][4][4];
#pragma unroll
    for (int i = 0; i < 4; i++)
#pragma unroll
        for (int j = 0; j < 4; j++)
#pragma unroll
            for (int q = 0; q < 4; q++) acc[i][j][q] = 0.f;

    // prefetch k-tile 0
    float4 va0 = *(const float4*)(Ag);
    float4 va1 = *(const float4*)(Ag + 4);
    float4 vb0 = *(const float4*)(Wg);
    float4 vb1 = *(const float4*)(Wg + 4);

    for (int kt = 0; kt < NK; kt++) {
        char* stg = sm + (kt & 1) * STG_BYTES;

        // ---- split current regs -> packed bf16 hi/lo tiles ----
        {
            uint32_t h[4], l[4];
            split8(va0, va1, h, l);
            *(uint4*)(stg + OFF_AH + st_off) = make_uint4(h[0], h[1], h[2], h[3]);
            *(uint4*)(stg + OFF_AL + st_off) = make_uint4(l[0], l[1], l[2], l[3]);
            split8(vb0, vb1, h, l);
            *(uint4*)(stg + OFF_BH + st_off) = make_uint4(h[0], h[1], h[2], h[3]);
            *(uint4*)(stg + OFF_BL + st_off) = make_uint4(l[0], l[1], l[2], l[3]);
        }
        __syncthreads();

        // ---- prefetch next tile during compute ----
        if (kt + 1 < NK) {
            const float* ag = Ag + (kt + 1) * BK;
            const float* wg = Wg + (kt + 1) * BK;
            va0 = *(const float4*)(ag);
            va1 = *(const float4*)(ag + 4);
            vb0 = *(const float4*)(wg);
            vb1 = *(const float4*)(wg + 4);
        }

        // ---- load fragments (pure LDS.b32, conflict-free) ----
        uint32_t ah[4][4], al[4][4], bh[4][2], bl[4][2];
#pragma unroll
        for (int mt = 0; mt < 4; mt++) {
            const int m0 = (wm * 64 + mt * 16 + qr) * ROWB + qc;
            const int m8 = m0 + 8 * ROWB;
            ah[mt][0] = *(const uint32_t*)(stg + OFF_AH + m0);
            ah[mt][1] = *(const uint32_t*)(stg + OFF_AH + m8);
            ah[mt][2] = *(const uint32_t*)(stg + OFF_AH + m0 + 16);
            ah[mt][3] = *(const uint32_t*)(stg + OFF_AH + m8 + 16);
            al[mt][0] = *(const uint32_t*)(stg + OFF_AL + m0);
            al[mt][1] = *(const uint32_t*)(stg + OFF_AL + m8);
            al[mt][2] = *(const uint32_t*)(stg + OFF_AL + m0 + 16);
            al[mt][3] = *(const uint32_t*)(stg + OFF_AL + m8 + 16);
        }
#pragma unroll
        for (int nt = 0; nt < 4; nt++) {
            const int n0 = (wn * 32 + nt * 8 + qr) * ROWB + qc;
            bh[nt][0] = *(const uint32_t*)(stg + OFF_BH + n0);
            bh[nt][1] = *(const uint32_t*)(stg + OFF_BH + n0 + 16);
            bl[nt][0] = *(const uint32_t*)(stg + OFF_BL + n0);
            bl[nt][1] = *(const uint32_t*)(stg + OFF_BL + n0 + 16);
        }

        // ---- 3 cross terms; same-acc reuse distance = 16 MMAs ----
#pragma unroll
        for (int nt = 0; nt < 4; nt++)
#pragma unroll
            for (int mt = 0; mt < 4; mt++) mma16816(acc[mt][nt], ah[mt], bh[nt]);
#pragma unroll
        for (int nt = 0; nt < 4; nt++)
#pragma unroll
            for (int mt = 0; mt < 4; mt++) mma16816(acc[mt][nt], al[mt], bh[nt]);
#pragma unroll
        for (int nt = 0; nt < 4; nt++)
#pragma unroll
            for (int mt = 0; mt < 4; mt++) mma16816(acc[mt][nt], ah[mt], bl[nt]);

        __syncthreads();
    }

    // ---- epilogue: c0,c1 at (r, col), c2,c3 at (r+8, col) ----
    const size_t gcol = (size_t)g * PK + bn;
#pragma unroll
    for (int mt = 0; mt < 4; mt++) {
        const int r0 = bm + wm * 64 + mt * 16 + qr;
#pragma unroll
        for (int nt = 0; nt < 4; nt++) {
            const int c0 = wn * 32 + nt * 8 + (lane & 3) * 2;
            float2 lo = make_float2(acc[mt][nt][0], acc[mt][nt][1]);
            float2 hi = make_float2(acc[mt][nt][2], acc[mt][nt][3]);
            *(float2*)(scores + (size_t)r0 * LDSC + gcol + c0)       = lo;
            *(float2*)(scores + (size_t)(r0 + 8) * LDSC + gcol + c0) = hi;
        }
    }
}

// ---------------------------------------------------------------------------
// Kernel 2: per (row, codebook): argmax over 8192 scores (first-index tie-break)
// then gather W[idx] into z_q_st and z_q. (82.8% DRAM — near roofline.)
// ---------------------------------------------------------------------------
__global__ __launch_bounds__(256)
void vq_argmax_gather_kernel(const float* __restrict__ scores,
                             const float* __restrict__ Wa,
                             const float* __restrict__ Wv,
                             float* __restrict__ out_st,
                             float* __restrict__ out_q)
{
    const int r = blockIdx.x;
    const int g = blockIdx.y;
    const int tid = threadIdx.x;

    const float* __restrict__ srow = scores + (size_t)r * LDSC + (size_t)g * PK;

    float best = -CUDART_INF_F;
    int   bidx = 0;
    for (int k = tid; k < PK; k += 256) {
        float v = srow[k];
        if (v > best) { best = v; bidx = k; }
    }

    __shared__ float sv[256];
    __shared__ int   si[256];
    sv[tid] = best;
    si[tid] = bidx;
    __syncthreads();

#pragma unroll
    for (int stride = 128; stride > 0; stride >>= 1) {
        if (tid < stride) {
            float v2 = sv[tid + stride];
            int   i2 = si[tid + stride];
            if (v2 > sv[tid] || (v2 == sv[tid] && i2 < si[tid])) {
                sv[tid] = v2;
                si[tid] = i2;
            }
        }
        __syncthreads();
    }
    const int idx = si[0];

    const float* __restrict__ Wrow = (g ? Wv : Wa) + (size_t)idx * PD;
    float* st = out_st + (size_t)r * LDZ + (size_t)g * PD;
    float* q  = out_q  + (size_t)r * LDZ + (size_t)g * PD;

    if (tid < 128) {
        float4 wv = *(const float4*)(Wrow + tid * 4);
        *(float4*)(st + tid * 4) = wv;
        *(float4*)(q  + tid * 4) = wv;
    }
}

// ---------------------------------------------------------------------------
// Harness entry
// ---------------------------------------------------------------------------
extern "C" void kernel_launch(void* const* d_in, const int* in_sizes, int n_in,
                              void* d_out, int out_size)
{
    const float* Z  = (const float*)d_in[0];  // [8192, 1024]
    const float* Wa = (const float*)d_in[1];  // [8192, 512]
    const float* Wv = (const float*)d_in[2];  // [8192, 512]

    float* out    = (float*)d_out;
    float* out_st = out;                         // [B, 2D]
    float* out_q  = out + (size_t)PB * LDZ;      // [B, 2D]
    float* scores = out + (size_t)2 * PB * LDZ;  // [B, 2K]

    dim3 ggrid(PK / BN, PB / BM, 2);   // (64, 64, 2)
    vq_gemm_bf16x2<<<ggrid, 256>>>(Z, Wa, Wv, scores);

    dim3 agrid(PB, 2);
    vq_argmax_gather_kernel<<<agrid, 256>>>(scores, Wa, Wv, out_st, out_q);
}

// round 8
// speedup vs baseline: 2.1649x; 1.4025x over previous
#include <cuda_runtime.h>
#include <math_constants.h>
#include <cstdint>

// ---------------- problem constants ----------------
#define PB 8192      // batch rows
#define PK 8192      // codebook size
#define PD 512       // dim per codebook
#define LDZ 1024     // z_e_x row stride (2*PD)
#define LDSC 16384   // scores row stride (2*PK)

// ---------------- GEMM tiling ----------------
#define BM 128
#define BN 128
#define BK 16
#define NK (PD / BK)     // 32 k-iterations
#define NSTG 3           // cp.async pipeline depth

// smem: bf16 tiles [row][k], 32B payload padded to 48B (12-word stride ->
// perfect 32-bank permutation for the 8x4 fragment access pattern)
#define ROWB 48
#define T_BYTES (128 * ROWB)      // 6144 per tile buffer
#define STG_BYTES (4 * T_BYTES)   // AH, AL, BH, BL = 24576
#define SMEM_TOTAL (NSTG * STG_BYTES)  // 73728
#define OFF_AH 0
#define OFF_AL (T_BYTES)
#define OFF_BH (2 * T_BYTES)
#define OFF_BL (3 * T_BYTES)

// ---------------- device scratch: pre-split bf16 operands ----------------
// Zh/Zl: [8192][1024]; Wh/Wl: [2][8192][512]
__device__ uint16_t g_Zh[(size_t)PB * LDZ];
__device__ uint16_t g_Zl[(size_t)PB * LDZ];
__device__ uint16_t g_Wh[(size_t)2 * PK * PD];
__device__ uint16_t g_Wl[(size_t)2 * PK * PD];

// ---------------- helpers ----------------
static __device__ __forceinline__ uint32_t pack_bf16(float lo, float hi) {
    uint32_t r;
    asm("cvt.rn.bf16x2.f32 %0, %1, %2;" : "=r"(r) : "f"(hi), "f"(lo));
    return r;
}

static __device__ __forceinline__ void mma16816(float* c, const uint32_t* a, const uint32_t* b) {
    asm volatile(
        "mma.sync.aligned.m16n8k16.row.col.f32.bf16.bf16.f32 "
        "{%0,%1,%2,%3}, {%4,%5,%6,%7}, {%8,%9}, {%0,%1,%2,%3};"
        : "+f"(c[0]), "+f"(c[1]), "+f"(c[2]), "+f"(c[3])
        : "r"(a[0]), "r"(a[1]), "r"(a[2]), "r"(a[3]), "r"(b[0]), "r"(b[1]));
}

static __device__ __forceinline__ uint32_t smem_u32(const void* p) {
    uint32_t a;
    asm("{ .reg .u64 t; cvta.to.shared.u64 t, %1; cvt.u32.u64 %0, t; }" : "=r"(a) : "l"(p));
    return a;
}
static __device__ __forceinline__ uint64_t glob_u64(const void* p) {
    uint64_t a;
    asm("cvta.to.global.u64 %0, %1;" : "=l"(a) : "l"(p));
    return a;
}
#define CP16(dst, src) \
    asm volatile("cp.async.cg.shared.global [%0], [%1], 16;" :: "r"(dst), "l"(src))
#define CP_COMMIT() asm volatile("cp.async.commit_group;" ::: "memory")
#define CP_WAIT1()  asm volatile("cp.async.wait_group 1;" ::: "memory")

// ---------------------------------------------------------------------------
// Kernel 0: split f32 -> bf16 hi + bf16 lo residual. 4 elems/thread.
// blockIdx.y: 0 -> Z (8M elems), 1 -> Wa, 2 -> Wv (4M each).
// ---------------------------------------------------------------------------
__global__ __launch_bounds__(256)
void split_kernel(const float* __restrict__ Z,
                  const float* __restrict__ Wa,
                  const float* __restrict__ Wv)
{
    const int region = blockIdx.y;
    const size_t i = ((size_t)blockIdx.x * 256 + threadIdx.x);   // quad index
    const size_t nquads = (region == 0) ? ((size_t)PB * LDZ / 4) : ((size_t)PK * PD / 4);
    if (i >= nquads) return;

    const float* src;
    uint16_t *dh, *dl;
    if (region == 0)      { src = Z;  dh = g_Zh; dl = g_Zl; }
    else if (region == 1) { src = Wa; dh = g_Wh; dl = g_Wl; }
    else                  { src = Wv; dh = g_Wh + (size_t)PK * PD; dl = g_Wl + (size_t)PK * PD; }

    float4 v = *(const float4*)(src + 4 * i);
    uint32_t h0 = pack_bf16(v.x, v.y);
    uint32_t h1 = pack_bf16(v.z, v.w);
    float r0 = v.x - __uint_as_float(h0 << 16);
    float r1 = v.y - __uint_as_float(h0 & 0xFFFF0000u);
    float r2 = v.z - __uint_as_float(h1 << 16);
    float r3 = v.w - __uint_as_float(h1 & 0xFFFF0000u);
    uint32_t l0 = pack_bf16(r0, r1);
    uint32_t l1 = pack_bf16(r2, r3);
    ((uint2*)dh)[i] = make_uint2(h0, h1);
    ((uint2*)dl)[i] = make_uint2(l0, l1);
}

// ---------------------------------------------------------------------------
// Kernel 1: split-bf16 (3-term) mma.sync dual-GEMM, cp.async 3-stage pipeline.
// CTA: 128x128 tile, 8 warps (warp tile 64x32).
// ---------------------------------------------------------------------------
__global__ __launch_bounds__(256, 1)
void vq_gemm_cp(float* __restrict__ scores)
{
    extern __shared__ __align__(16) char sm[];
    const uint32_t sb = smem_u32(sm);

    const int tid  = threadIdx.x;
    const int lane = tid & 31;
    const int w    = tid >> 5;
    const int wm   = w >> 2;   // 0..1 -> 64-row slab
    const int wn   = w & 3;    // 0..3 -> 32-col slab
    const int g    = blockIdx.z;
    const int bm   = blockIdx.y * BM;
    const int bn   = blockIdx.x * BN;

    // loader mapping: thread covers row tid>>1, 16B chunk (tid&1) of the 32B row
    const int lr = tid >> 1;
    const int kh = tid & 1;
    const uint64_t srcAH = glob_u64(g_Zh + (size_t)(bm + lr) * LDZ + g * PD + kh * 8);
    const uint64_t srcAL = glob_u64(g_Zl + (size_t)(bm + lr) * LDZ + g * PD + kh * 8);
    const uint64_t srcBH = glob_u64(g_Wh + ((size_t)g * PK + bn + lr) * PD + kh * 8);
    const uint64_t srcBL = glob_u64(g_Wl + ((size_t)g * PK + bn + lr) * PD + kh * 8);
    const uint32_t doff = (uint32_t)(lr * ROWB + kh * 16);

    const int qr = lane >> 2;        // 0..7
    const int qc = (lane & 3) * 4;   // word byte-offset 0..12

    float acc[4][4][4];
#pragma unroll
    for (int i = 0; i < 4; i++)
#pragma unroll
        for (int j = 0; j < 4; j++)
#pragma unroll
            for (int q = 0; q < 4; q++) acc[i][j][q] = 0.f;

#define ISSUE(slot, kt_) do {                                            \
    const uint32_t st_ = sb + (slot) * STG_BYTES + doff;                 \
    const uint64_t kb_ = (uint64_t)(kt_) * 32;  /* 16 elems * 2B */      \
    CP16(st_ + OFF_AH, srcAH + kb_);                                     \
    CP16(st_ + OFF_AL, srcAL + kb_);                                     \
    CP16(st_ + OFF_BH, srcBH + kb_);                                     \
    CP16(st_ + OFF_BL, srcBL + kb_);                                     \
} while (0)

    // prologue: stages 0,1 in flight
    ISSUE(0, 0); CP_COMMIT();
    ISSUE(1, 1); CP_COMMIT();

    int sc = 0;   // compute slot
    int si = 2;   // issue slot
    for (int kt = 0; kt < NK; kt++) {
        CP_WAIT1();
        __syncthreads();

        if (kt + 2 < NK) ISSUE(si, kt + 2);
        CP_COMMIT();   // commit every iteration (empty tail groups keep count aligned)
        if (++si == NSTG) si = 0;

        const char* stg = sm + sc * STG_BYTES;
        if (++sc == NSTG) sc = 0;

        // ---- fragment loads (LDS.b32, conflict-free via 48B row stride) ----
        uint32_t ah[4][4], al[4][4], bh[4][2], bl[4][2];
#pragma unroll
        for (int mt = 0; mt < 4; mt++) {
            const int m0 = (wm * 64 + mt * 16 + qr) * ROWB + qc;
            const int m8 = m0 + 8 * ROWB;
            ah[mt][0] = *(const uint32_t*)(stg + OFF_AH + m0);
            ah[mt][1] = *(const uint32_t*)(stg + OFF_AH + m8);
            ah[mt][2] = *(const uint32_t*)(stg + OFF_AH + m0 + 16);
            ah[mt][3] = *(const uint32_t*)(stg + OFF_AH + m8 + 16);
            al[mt][0] = *(const uint32_t*)(stg + OFF_AL + m0);
            al[mt][1] = *(const uint32_t*)(stg + OFF_AL + m8);
            al[mt][2] = *(const uint32_t*)(stg + OFF_AL + m0 + 16);
            al[mt][3] = *(const uint32_t*)(stg + OFF_AL + m8 + 16);
        }
#pragma unroll
        for (int nt = 0; nt < 4; nt++) {
            const int n0 = (wn * 32 + nt * 8 + qr) * ROWB + qc;
            bh[nt][0] = *(const uint32_t*)(stg + OFF_BH + n0);
            bh[nt][1] = *(const uint32_t*)(stg + OFF_BH + n0 + 16);
            bl[nt][0] = *(const uint32_t*)(stg + OFF_BL + n0);
            bl[nt][1] = *(const uint32_t*)(stg + OFF_BL + n0 + 16);
        }

        // ---- 3 cross terms; same-acc reuse distance = 16 MMAs ----
#pragma unroll
        for (int nt = 0; nt < 4; nt++)
#pragma unroll
            for (int mt = 0; mt < 4; mt++) mma16816(acc[mt][nt], ah[mt], bh[nt]);
#pragma unroll
        for (int nt = 0; nt < 4; nt++)
#pragma unroll
            for (int mt = 0; mt < 4; mt++) mma16816(acc[mt][nt], al[mt], bh[nt]);
#pragma unroll
        for (int nt = 0; nt < 4; nt++)
#pragma unroll
            for (int mt = 0; mt < 4; mt++) mma16816(acc[mt][nt], ah[mt], bl[nt]);
    }
#undef ISSUE

    // ---- epilogue: c0,c1 at (r, col), c2,c3 at (r+8, col) ----
    const size_t gcol = (size_t)g * PK + bn;
#pragma unroll
    for (int mt = 0; mt < 4; mt++) {
        const int r0 = bm + wm * 64 + mt * 16 + qr;
#pragma unroll
        for (int nt = 0; nt < 4; nt++) {
            const int c0 = wn * 32 + nt * 8 + (lane & 3) * 2;
            float2 lo = make_float2(acc[mt][nt][0], acc[mt][nt][1]);
            float2 hi = make_float2(acc[mt][nt][2], acc[mt][nt][3]);
            *(float2*)(scores + (size_t)r0 * LDSC + gcol + c0)       = lo;
            *(float2*)(scores + (size_t)(r0 + 8) * LDSC + gcol + c0) = hi;
        }
    }
}

// ---------------------------------------------------------------------------
// Kernel 2: per (row, codebook): argmax over 8192 scores (first-index
// tie-break) then gather W[idx]. 82.5% DRAM — near its roofline, unchanged.
// ---------------------------------------------------------------------------
__global__ __launch_bounds__(256)
void vq_argmax_gather_kernel(const float* __restrict__ scores,
                             const float* __restrict__ Wa,
                             const float* __restrict__ Wv,
                             float* __restrict__ out_st,
                             float* __restrict__ out_q)
{
    const int r = blockIdx.x;
    const int g = blockIdx.y;
    const int tid = threadIdx.x;

    const float* __restrict__ srow = scores + (size_t)r * LDSC + (size_t)g * PK;

    float best = -CUDART_INF_F;
    int   bidx = 0;
    for (int k = tid; k < PK; k += 256) {
        float v = srow[k];
        if (v > best) { best = v; bidx = k; }
    }

    __shared__ float sv[256];
    __shared__ int   si[256];
    sv[tid] = best;
    si[tid] = bidx;
    __syncthreads();

#pragma unroll
    for (int stride = 128; stride > 0; stride >>= 1) {
        if (tid < stride) {
            float v2 = sv[tid + stride];
            int   i2 = si[tid + stride];
            if (v2 > sv[tid] || (v2 == sv[tid] && i2 < si[tid])) {
                sv[tid] = v2;
                si[tid] = i2;
            }
        }
        __syncthreads();
    }
    const int idx = si[0];

    const float* __restrict__ Wrow = (g ? Wv : Wa) + (size_t)idx * PD;
    float* st = out_st + (size_t)r * LDZ + (size_t)g * PD;
    float* q  = out_q  + (size_t)r * LDZ + (size_t)g * PD;

    if (tid < 128) {
        float4 wv = *(const float4*)(Wrow + tid * 4);
        *(float4*)(st + tid * 4) = wv;
        *(float4*)(q  + tid * 4) = wv;
    }
}

// ---------------------------------------------------------------------------
// Harness entry
// ---------------------------------------------------------------------------
extern "C" void kernel_launch(void* const* d_in, const int* in_sizes, int n_in,
                              void* d_out, int out_size)
{
    const float* Z  = (const float*)d_in[0];  // [8192, 1024]
    const float* Wa = (const float*)d_in[1];  // [8192, 512]
    const float* Wv = (const float*)d_in[2];  // [8192, 512]

    float* out    = (float*)d_out;
    float* out_st = out;                         // [B, 2D]
    float* out_q  = out + (size_t)PB * LDZ;      // [B, 2D]
    float* scores = out + (size_t)2 * PB * LDZ;  // [B, 2K]

    static int smem_set = 0;
    if (!smem_set) {
        cudaFuncSetAttribute(vq_gemm_cp, cudaFuncAttributeMaxDynamicSharedMemorySize,
                             SMEM_TOTAL);
        smem_set = 1;
    }

    // pre-split: Z -> 8192 x-blocks; W books guarded inside
    dim3 sgrid((unsigned)(((size_t)PB * LDZ / 4 + 255) / 256), 3);
    split_kernel<<<sgrid, 256>>>(Z, Wa, Wv);

    dim3 ggrid(PK / BN, PB / BM, 2);   // (64, 64, 2)
    vq_gemm_cp<<<ggrid, 256, SMEM_TOTAL>>>(scores);

    dim3 agrid(PB, 2);
    vq_argmax_gather_kernel<<<agrid, 256>>>(scores, Wa, Wv, out_st, out_q);
}